// round 12
// baseline (speedup 1.0000x reference)
#include <cuda_runtime.h>
#include <cuda_fp16.h>
#include <cstdint>

// ============================================================================
// out[8192,2048] = x[8192,2048] @ W[2048,2048]^T + bias
// fp16 single-term GEMM on HMMA (mma.sync m16n8k16.f32.f16.f16.f32).
// R12: cross-CTA split-K2 to kill wave quantization.
//   - R9's proven CTA shape: 128 thr, tile 128x128, KT=64, 3-stage cp.async,
//     96KB smem, 2 CTAs/SM, warp tile 64x64, stage-head reorder (74.7% tensor).
//   - grid 2048 = 1024 tiles x 2 k-halves -> 6.92 waves (92%-full last wave)
//     vs R9's 3.46 -> 4 (13.5% quant loss).
//   - init kernel: out = bias (stream-ordered), then both halves REDG-add.
// ============================================================================

#define M_TOTAL 8192
#define N_TOTAL 2048
#define K_TOTAL 2048

#define MT 128
#define NT 128
#define KT 64
#define K_GROUP 1024            // K per CTA (k-half)
#define KITERS (K_GROUP / KT)   // 16
#define NSTAGE 3

#define M_TILES (M_TOTAL / MT)  // 64
#define N_TILES (N_TOTAL / NT)  // 16
#define NUM_TILES (M_TILES * N_TILES)   // 1024

#define OFF_A 0
#define OFF_B 16384
#define STAGE_BYTES 32768
#define SMEM_REQ (NSTAGE * STAGE_BYTES)   // 98304

__device__ __half g_xh[M_TOTAL * K_TOTAL];
__device__ __half g_wh[N_TOTAL * K_TOTAL];

// ---------------------------------------------------------------------------
__device__ __forceinline__ uint32_t smem_u32(const void* p) {
    uint32_t a;
    asm("{ .reg .u64 t; cvta.to.shared.u64 t, %1; cvt.u32.u64 %0, t; }"
        : "=r"(a) : "l"(p));
    return a;
}

__device__ __forceinline__ void cp_async16(uint32_t dst, const void* src) {
    asm volatile("cp.async.cg.shared.global [%0], [%1], 16;"
                 :: "r"(dst), "l"(src));
}
#define CP_COMMIT() asm volatile("cp.async.commit_group;" ::: "memory")
#define CP_WAIT1()  asm volatile("cp.async.wait_group 1;" ::: "memory")

__device__ __forceinline__ void ldsm_x4(uint32_t* r, uint32_t addr) {
    asm volatile("ldmatrix.sync.aligned.m8n8.x4.shared.b16 {%0,%1,%2,%3}, [%4];"
                 : "=r"(r[0]), "=r"(r[1]), "=r"(r[2]), "=r"(r[3])
                 : "r"(addr));
}

__device__ __forceinline__ void mma16816(float* c, const uint32_t* a, const uint32_t* b) {
    asm volatile(
        "mma.sync.aligned.m16n8k16.row.col.f32.f16.f16.f32 "
        "{%0,%1,%2,%3}, {%4,%5,%6,%7}, {%8,%9}, {%0,%1,%2,%3};"
        : "+f"(c[0]), "+f"(c[1]), "+f"(c[2]), "+f"(c[3])
        : "r"(a[0]), "r"(a[1]), "r"(a[2]), "r"(a[3]),
          "r"(b[0]), "r"(b[1]));
}

__device__ __forceinline__ void redg_add_f32(float* addr, float v) {
    asm volatile("red.global.add.f32 [%0], %1;" :: "l"(addr), "f"(v) : "memory");
}

// ---------------------------------------------------------------------------
// Kernel 0: out = bias (broadcast rows), float4 stores.
// ---------------------------------------------------------------------------
__global__ void __launch_bounds__(256) init_out_kernel(
    float4* __restrict__ out, const float4* __restrict__ bias4)
{
    int i = blockIdx.x * blockDim.x + threadIdx.x;   // 4M float4
    out[i] = __ldg(bias4 + (i & (N_TOTAL / 4 - 1)));
}

// ---------------------------------------------------------------------------
// Kernel 1: convert fp32 -> fp16 for BOTH x and W in one launch.
// ---------------------------------------------------------------------------
__global__ void __launch_bounds__(256) convert_both_kernel(
    const float4* __restrict__ srcx, float4* __restrict__ dstx, int n16x,
    const float4* __restrict__ srcw, float4* __restrict__ dstw, int n16w)
{
    int i = blockIdx.x * blockDim.x + threadIdx.x;
    const float4* src;
    float4* dst;
    if (i < n16x) {
        src = srcx + 4 * (size_t)i;
        dst = dstx + 2 * (size_t)i;
    } else {
        int j = i - n16x;
        if (j >= n16w) return;
        src = srcw + 4 * (size_t)j;
        dst = dstw + 2 * (size_t)j;
    }
    float4 v0 = src[0];
    float4 v1 = src[1];
    float4 v2 = src[2];
    float4 v3 = src[3];

    __half2 h0 = __halves2half2(__float2half_rn(v0.x), __float2half_rn(v0.y));
    __half2 h1 = __halves2half2(__float2half_rn(v0.z), __float2half_rn(v0.w));
    __half2 h2 = __halves2half2(__float2half_rn(v1.x), __float2half_rn(v1.y));
    __half2 h3 = __halves2half2(__float2half_rn(v1.z), __float2half_rn(v1.w));
    __half2 h4 = __halves2half2(__float2half_rn(v2.x), __float2half_rn(v2.y));
    __half2 h5 = __halves2half2(__float2half_rn(v2.z), __float2half_rn(v2.w));
    __half2 h6 = __halves2half2(__float2half_rn(v3.x), __float2half_rn(v3.y));
    __half2 h7 = __halves2half2(__float2half_rn(v3.z), __float2half_rn(v3.w));

    float4 o0, o1;
    o0.x = __uint_as_float(*(uint32_t*)&h0);
    o0.y = __uint_as_float(*(uint32_t*)&h1);
    o0.z = __uint_as_float(*(uint32_t*)&h2);
    o0.w = __uint_as_float(*(uint32_t*)&h3);
    o1.x = __uint_as_float(*(uint32_t*)&h4);
    o1.y = __uint_as_float(*(uint32_t*)&h5);
    o1.z = __uint_as_float(*(uint32_t*)&h6);
    o1.w = __uint_as_float(*(uint32_t*)&h7);
    dst[0] = o0;
    dst[1] = o1;
}

// ---------------------------------------------------------------------------
// Kernel 2: fp16 GEMM — R9 CTA shape, split-K2, REDG epilogue.
// ---------------------------------------------------------------------------
__global__ void __launch_bounds__(128, 2) fp16_gemm_kernel(
    float* __restrict__ out,
    const __half* __restrict__ xh,
    const __half* __restrict__ wh)
{
    extern __shared__ __align__(1024) char smem[];
    const uint32_t sb = smem_u32(smem);

    const int tid = threadIdx.x;
    const int lane = tid & 31;
    const int wid = tid >> 5;
    const int warp_m = wid >> 1;   // 0..1
    const int warp_n = wid & 1;    // 0..1

    const int bid = blockIdx.x;
    const int tile = bid & (NUM_TILES - 1);
    const int kg = bid >> 10;              // k-half 0 / 1
    const int n_tile = tile & (N_TILES - 1);
    const int m_tile = tile >> 4;
    const int m0 = m_tile * MT;
    const int n0 = n_tile * NT;
    const int k_base = kg * K_GROUP;

    // ---- register-compressed loader layout ----
    const int lrow = tid >> 3;
    const int lchk = tid & 7;
    const uint32_t dsw0 = (uint32_t)(lrow * 128 + ((lchk ^ (lrow & 7)) << 4));
    const __half* gA0 = xh + (size_t)(m0 + lrow) * K_TOTAL + k_base + lchk * 8;
    const __half* gB0 = wh + (size_t)(n0 + lrow) * K_TOTAL + k_base + lchk * 8;

    auto load_stage = [&](int stage, int k0) {
        uint32_t sbase = sb + stage * STAGE_BYTES + dsw0;
        const __half* pA = gA0 + k0;
        const __half* pB = gB0 + k0;
#pragma unroll
        for (int i = 0; i < 8; i++) {
            cp_async16(sbase + OFF_A + i * 2048, pA + (size_t)i * (16 * K_TOTAL));
            cp_async16(sbase + OFF_B + i * 2048, pB + (size_t)i * (16 * K_TOTAL));
        }
    };

    // ---- ldmatrix per-lane base terms ----
    const int a_row_l = warp_m * 64 + (lane & 15);
    const int a_kadd  = lane >> 4;
    const int b_row_l = warp_n * 64 + (lane & 7) + ((lane >> 4) << 3);
    const int b_kadd  = (lane >> 3) & 1;

    float acc[4][8][4];
#pragma unroll
    for (int mt = 0; mt < 4; mt++)
#pragma unroll
        for (int nt = 0; nt < 8; nt++)
#pragma unroll
            for (int j = 0; j < 4; j++) acc[mt][nt][j] = 0.0f;

    // ---- prologue ----
    load_stage(0, 0);
    CP_COMMIT();
    load_stage(1, KT);
    CP_COMMIT();

    uint32_t a[4][4], b[8][2];

    auto ld_frags = [&](int kc, uint32_t sA, uint32_t sB) {
#pragma unroll
        for (int mt = 0; mt < 4; mt++) {
            int row = a_row_l + mt * 16;
            int ch = kc * 2 + a_kadd;
            uint32_t off = (uint32_t)(row * 128 + ((ch ^ (row & 7)) << 4));
            ldsm_x4(a[mt], sA + off);
        }
#pragma unroll
        for (int np = 0; np < 4; np++) {
            int row = b_row_l + np * 16;
            int ch = kc * 2 + b_kadd;
            uint32_t off = (uint32_t)(row * 128 + ((ch ^ (row & 7)) << 4));
            uint32_t t[4];
            ldsm_x4(t, sB + off);
            b[np * 2][0] = t[0]; b[np * 2][1] = t[1];
            b[np * 2 + 1][0] = t[2]; b[np * 2 + 1][1] = t[3];
        }
    };

    // ---- mainloop (16 iterations) ----
    for (int ks = 0; ks < KITERS; ks++) {
        CP_WAIT1();
        __syncthreads();

        const uint32_t sbase = sb + (ks % NSTAGE) * STAGE_BYTES;
        const uint32_t sA = sbase + OFF_A;
        const uint32_t sB = sbase + OFF_B;

        // kc0 frag loads first: cp.async burst runs in their shadow
        ld_frags(0, sA, sB);

        if (ks + 2 < KITERS) load_stage((ks + 2) % NSTAGE, (ks + 2) * KT);
        CP_COMMIT();

#pragma unroll
        for (int kc = 0; kc < 4; kc++) {
#pragma unroll
            for (int mt = 0; mt < 4; mt++) {
#pragma unroll
                for (int nt = 0; nt < 8; nt++) {
                    mma16816(acc[mt][nt], a[mt], b[nt]);
                }
            }
            if (kc < 3) ld_frags(kc + 1, sA, sB);
        }
    }

    // ---- epilogue: REDG-add partials into bias-initialized out ----
    const int r0 = lane >> 2;
    const int c0 = (lane & 3) * 2;
#pragma unroll
    for (int mt = 0; mt < 4; mt++) {
        int row = m0 + warp_m * 64 + mt * 16 + r0;
#pragma unroll
        for (int nt = 0; nt < 8; nt++) {
            int col = n0 + warp_n * 64 + nt * 8 + c0;
            float* p0 = out + (size_t)row * N_TOTAL + col;
            float* p1 = out + (size_t)(row + 8) * N_TOTAL + col;
            redg_add_f32(p0,     acc[mt][nt][0]);
            redg_add_f32(p0 + 1, acc[mt][nt][1]);
            redg_add_f32(p1,     acc[mt][nt][2]);
            redg_add_f32(p1 + 1, acc[mt][nt][3]);
        }
    }
}

// ---------------------------------------------------------------------------
// Host side
// ---------------------------------------------------------------------------
extern "C" void kernel_launch(void* const* d_in, const int* in_sizes, int n_in,
                              void* d_out, int out_size) {
    const float* x    = (const float*)d_in[0];
    const float* w    = (const float*)d_in[1];
    const float* bias = (const float*)d_in[2];
    float* out = (float*)d_out;

    __half *xh, *wh;
    cudaGetSymbolAddress((void**)&xh, g_xh);
    cudaGetSymbolAddress((void**)&wh, g_wh);

    // 0. out = bias (must precede GEMM REDG adds; stream-ordered)
    {
        int n4 = (M_TOTAL * N_TOTAL) / 4;   // 4,194,304
        init_out_kernel<<<n4 / 256, 256>>>((float4*)out, (const float4*)bias);
    }

    // 1. convert x, W to fp16
    {
        int n16x = (M_TOTAL * K_TOTAL) / 16;   // 1,048,576
        int n16w = (N_TOTAL * K_TOTAL) / 16;   //   262,144
        int total = n16x + n16w;
        convert_both_kernel<<<(total + 255) / 256, 256>>>(
            (const float4*)x, (float4*)xh, n16x,
            (const float4*)w, (float4*)wh, n16w);
    }

    // 2. GEMM, split-K2
    static bool attr_set = false;
    if (!attr_set) {
        cudaFuncSetAttribute(fp16_gemm_kernel,
                             cudaFuncAttributeMaxDynamicSharedMemorySize, SMEM_REQ);
        attr_set = true;
    }
    fp16_gemm_kernel<<<2 * NUM_TILES, 128, SMEM_REQ>>>(out, xh, wh);
}

// round 13
// speedup vs baseline: 1.0957x; 1.0957x over previous
#include <cuda_runtime.h>
#include <cuda_fp16.h>
#include <cstdint>

// ============================================================================
// out[8192,2048] = x[8192,2048] @ W[2048,2048]^T + bias
// fp16 single-term GEMM on HMMA (mma.sync m16n8k16.f32.f16.f16.f32).
// R13: tail-only split-K.
//   1024 tiles = 888 full-K (3 exact waves of 296) + 136 tail tiles as
//   272 half-K CTAs (0.92-wave short tail). Combine tax scoped to the tail:
//   2us region init + 4.5M REDG. Mainloop/CTA shape = R9 verbatim
//   (128 thr, 128x128, KT=64, 3-stage, 96KB, 2 CTAs/SM, stage-head reorder).
// ============================================================================

#define M_TOTAL 8192
#define N_TOTAL 2048
#define K_TOTAL 2048

#define MT 128
#define NT 128
#define KT 64
#define NSTAGE 3

#define M_TILES (M_TOTAL / MT)  // 64
#define N_TILES (N_TOTAL / NT)  // 16
#define NUM_TILES (M_TILES * N_TILES)   // 1024

#define SPLIT_START 888          // tiles [888,1024) are split-K2
#define NSPLIT (NUM_TILES - SPLIT_START)   // 136
#define GRID_SIZE (SPLIT_START + 2 * NSPLIT)  // 1160

#define OFF_A 0
#define OFF_B 16384
#define STAGE_BYTES 32768
#define SMEM_REQ (NSTAGE * STAGE_BYTES)   // 98304

__device__ __half g_xh[M_TOTAL * K_TOTAL];
__device__ __half g_wh[N_TOTAL * K_TOTAL];

// ---------------------------------------------------------------------------
__device__ __forceinline__ uint32_t smem_u32(const void* p) {
    uint32_t a;
    asm("{ .reg .u64 t; cvta.to.shared.u64 t, %1; cvt.u32.u64 %0, t; }"
        : "=r"(a) : "l"(p));
    return a;
}

__device__ __forceinline__ void cp_async16(uint32_t dst, const void* src) {
    asm volatile("cp.async.cg.shared.global [%0], [%1], 16;"
                 :: "r"(dst), "l"(src));
}
#define CP_COMMIT() asm volatile("cp.async.commit_group;" ::: "memory")
#define CP_WAIT1()  asm volatile("cp.async.wait_group 1;" ::: "memory")

__device__ __forceinline__ void ldsm_x4(uint32_t* r, uint32_t addr) {
    asm volatile("ldmatrix.sync.aligned.m8n8.x4.shared.b16 {%0,%1,%2,%3}, [%4];"
                 : "=r"(r[0]), "=r"(r[1]), "=r"(r[2]), "=r"(r[3])
                 : "r"(addr));
}

__device__ __forceinline__ void mma16816(float* c, const uint32_t* a, const uint32_t* b) {
    asm volatile(
        "mma.sync.aligned.m16n8k16.row.col.f32.f16.f16.f32 "
        "{%0,%1,%2,%3}, {%4,%5,%6,%7}, {%8,%9}, {%0,%1,%2,%3};"
        : "+f"(c[0]), "+f"(c[1]), "+f"(c[2]), "+f"(c[3])
        : "r"(a[0]), "r"(a[1]), "r"(a[2]), "r"(a[3]),
          "r"(b[0]), "r"(b[1]));
}

__device__ __forceinline__ void redg_add_f32(float* addr, float v) {
    asm volatile("red.global.add.f32 [%0], %1;" :: "l"(addr), "f"(v) : "memory");
}

// ---------------------------------------------------------------------------
// Kernel 0: pre-fill the tail-tile region of `out` with bias.
//   Region A: tiles 888..895  -> rows [7040,7168), cols [1024,2048)
//   Region B: tiles 896..1023 -> rows [7168,8192), cols [0,2048)
// ---------------------------------------------------------------------------
#define A4_COUNT (128 * 256)      // region A in float4 units: 32768
#define B4_COUNT (1024 * 512)     // region B: 524288

__global__ void __launch_bounds__(256) init_tail_kernel(
    float4* __restrict__ out4, const float4* __restrict__ bias4)
{
    int i = blockIdx.x * blockDim.x + threadIdx.x;
    int row, col4;
    if (i < A4_COUNT) {
        row  = 7040 + (i >> 8);          // 256 float4 per row slice
        col4 = 256 + (i & 255);          // cols 1024..2047
    } else {
        int j = i - A4_COUNT;
        if (j >= B4_COUNT) return;
        row  = 7168 + (j >> 9);          // 512 float4 per row
        col4 = j & 511;
    }
    out4[(size_t)row * (N_TOTAL / 4) + col4] = __ldg(bias4 + col4);
}

// ---------------------------------------------------------------------------
// Kernel 1: convert fp32 -> fp16 for BOTH x and W in one launch.
// ---------------------------------------------------------------------------
__global__ void __launch_bounds__(256) convert_both_kernel(
    const float4* __restrict__ srcx, float4* __restrict__ dstx, int n16x,
    const float4* __restrict__ srcw, float4* __restrict__ dstw, int n16w)
{
    int i = blockIdx.x * blockDim.x + threadIdx.x;
    const float4* src;
    float4* dst;
    if (i < n16x) {
        src = srcx + 4 * (size_t)i;
        dst = dstx + 2 * (size_t)i;
    } else {
        int j = i - n16x;
        if (j >= n16w) return;
        src = srcw + 4 * (size_t)j;
        dst = dstw + 2 * (size_t)j;
    }
    float4 v0 = src[0];
    float4 v1 = src[1];
    float4 v2 = src[2];
    float4 v3 = src[3];

    __half2 h0 = __halves2half2(__float2half_rn(v0.x), __float2half_rn(v0.y));
    __half2 h1 = __halves2half2(__float2half_rn(v0.z), __float2half_rn(v0.w));
    __half2 h2 = __halves2half2(__float2half_rn(v1.x), __float2half_rn(v1.y));
    __half2 h3 = __halves2half2(__float2half_rn(v1.z), __float2half_rn(v1.w));
    __half2 h4 = __halves2half2(__float2half_rn(v2.x), __float2half_rn(v2.y));
    __half2 h5 = __halves2half2(__float2half_rn(v2.z), __float2half_rn(v2.w));
    __half2 h6 = __halves2half2(__float2half_rn(v3.x), __float2half_rn(v3.y));
    __half2 h7 = __halves2half2(__float2half_rn(v3.z), __float2half_rn(v3.w));

    float4 o0, o1;
    o0.x = __uint_as_float(*(uint32_t*)&h0);
    o0.y = __uint_as_float(*(uint32_t*)&h1);
    o0.z = __uint_as_float(*(uint32_t*)&h2);
    o0.w = __uint_as_float(*(uint32_t*)&h3);
    o1.x = __uint_as_float(*(uint32_t*)&h4);
    o1.y = __uint_as_float(*(uint32_t*)&h5);
    o1.z = __uint_as_float(*(uint32_t*)&h6);
    o1.w = __uint_as_float(*(uint32_t*)&h7);
    dst[0] = o0;
    dst[1] = o1;
}

// ---------------------------------------------------------------------------
// Kernel 2: fp16 GEMM — R9 mainloop; full-K tiles + split-K2 tail tiles.
// ---------------------------------------------------------------------------
__global__ void __launch_bounds__(128, 2) fp16_gemm_kernel(
    float* __restrict__ out,
    const float* __restrict__ bias,
    const __half* __restrict__ xh,
    const __half* __restrict__ wh)
{
    extern __shared__ __align__(1024) char smem[];
    const uint32_t sb = smem_u32(smem);

    const int tid = threadIdx.x;
    const int lane = tid & 31;
    const int wid = tid >> 5;
    const int warp_m = wid >> 1;   // 0..1
    const int warp_n = wid & 1;    // 0..1

    // ---- tile / k-range decode ----
    const int bid = blockIdx.x;
    int tile, kiters, k_base;
    bool is_split;
    if (bid < SPLIT_START) {
        tile = bid;  kiters = 32;  k_base = 0;  is_split = false;
    } else {
        int idx = bid - SPLIT_START;
        int kg = (idx >= NSPLIT) ? 1 : 0;
        tile = SPLIT_START + (idx - kg * NSPLIT);
        kiters = 16;  k_base = kg * 1024;  is_split = true;
    }
    const int n_tile = tile & (N_TILES - 1);
    const int m_tile = tile >> 4;
    const int m0 = m_tile * MT;
    const int n0 = n_tile * NT;

    // ---- register-compressed loader layout ----
    const int lrow = tid >> 3;
    const int lchk = tid & 7;
    const uint32_t dsw0 = (uint32_t)(lrow * 128 + ((lchk ^ (lrow & 7)) << 4));
    const __half* gA0 = xh + (size_t)(m0 + lrow) * K_TOTAL + k_base + lchk * 8;
    const __half* gB0 = wh + (size_t)(n0 + lrow) * K_TOTAL + k_base + lchk * 8;

    auto load_stage = [&](int stage, int k0) {
        uint32_t sbase = sb + stage * STAGE_BYTES + dsw0;
        const __half* pA = gA0 + k0;
        const __half* pB = gB0 + k0;
#pragma unroll
        for (int i = 0; i < 8; i++) {
            cp_async16(sbase + OFF_A + i * 2048, pA + (size_t)i * (16 * K_TOTAL));
            cp_async16(sbase + OFF_B + i * 2048, pB + (size_t)i * (16 * K_TOTAL));
        }
    };

    // ---- ldmatrix per-lane base terms ----
    const int a_row_l = warp_m * 64 + (lane & 15);
    const int a_kadd  = lane >> 4;
    const int b_row_l = warp_n * 64 + (lane & 7) + ((lane >> 4) << 3);
    const int b_kadd  = (lane >> 3) & 1;

    float acc[4][8][4];
#pragma unroll
    for (int mt = 0; mt < 4; mt++)
#pragma unroll
        for (int nt = 0; nt < 8; nt++)
#pragma unroll
            for (int j = 0; j < 4; j++) acc[mt][nt][j] = 0.0f;

    // ---- prologue ----
    load_stage(0, 0);
    CP_COMMIT();
    load_stage(1, KT);
    CP_COMMIT();

    uint32_t a[4][4], b[8][2];

    auto ld_frags = [&](int kc, uint32_t sA, uint32_t sB) {
#pragma unroll
        for (int mt = 0; mt < 4; mt++) {
            int row = a_row_l + mt * 16;
            int ch = kc * 2 + a_kadd;
            uint32_t off = (uint32_t)(row * 128 + ((ch ^ (row & 7)) << 4));
            ldsm_x4(a[mt], sA + off);
        }
#pragma unroll
        for (int np = 0; np < 4; np++) {
            int row = b_row_l + np * 16;
            int ch = kc * 2 + b_kadd;
            uint32_t off = (uint32_t)(row * 128 + ((ch ^ (row & 7)) << 4));
            uint32_t t[4];
            ldsm_x4(t, sB + off);
            b[np * 2][0] = t[0]; b[np * 2][1] = t[1];
            b[np * 2 + 1][0] = t[2]; b[np * 2 + 1][1] = t[3];
        }
    };

    // ---- mainloop ----
    for (int ks = 0; ks < kiters; ks++) {
        CP_WAIT1();
        __syncthreads();

        const uint32_t sbase = sb + (ks % NSTAGE) * STAGE_BYTES;
        const uint32_t sA = sbase + OFF_A;
        const uint32_t sB = sbase + OFF_B;

        // kc0 frag loads first: cp.async burst runs in their shadow
        ld_frags(0, sA, sB);

        if (ks + 2 < kiters) load_stage((ks + 2) % NSTAGE, (ks + 2) * KT);
        CP_COMMIT();

#pragma unroll
        for (int kc = 0; kc < 4; kc++) {
#pragma unroll
            for (int mt = 0; mt < 4; mt++) {
#pragma unroll
                for (int nt = 0; nt < 8; nt++) {
                    mma16816(acc[mt][nt], a[mt], b[nt]);
                }
            }
            if (kc < 3) ld_frags(kc + 1, sA, sB);
        }
    }

    // ---- epilogue ----
    const int r0 = lane >> 2;
    const int c0 = (lane & 3) * 2;
    if (!is_split) {
        // full tile: store with bias (R9 epilogue)
#pragma unroll
        for (int mt = 0; mt < 4; mt++) {
            int row = m0 + warp_m * 64 + mt * 16 + r0;
#pragma unroll
            for (int nt = 0; nt < 8; nt++) {
                int col = n0 + warp_n * 64 + nt * 8 + c0;
                float bx = __ldg(bias + col);
                float by = __ldg(bias + col + 1);
                float2 v0 = make_float2(acc[mt][nt][0] + bx, acc[mt][nt][1] + by);
                float2 v1 = make_float2(acc[mt][nt][2] + bx, acc[mt][nt][3] + by);
                *(float2*)(out + (size_t)row * N_TOTAL + col) = v0;
                *(float2*)(out + (size_t)(row + 8) * N_TOTAL + col) = v1;
            }
        }
    } else {
        // split tile: REDG-add partial into bias-pre-initialized out
#pragma unroll
        for (int mt = 0; mt < 4; mt++) {
            int row = m0 + warp_m * 64 + mt * 16 + r0;
#pragma unroll
            for (int nt = 0; nt < 8; nt++) {
                int col = n0 + warp_n * 64 + nt * 8 + c0;
                float* p0 = out + (size_t)row * N_TOTAL + col;
                float* p1 = out + (size_t)(row + 8) * N_TOTAL + col;
                redg_add_f32(p0,     acc[mt][nt][0]);
                redg_add_f32(p0 + 1, acc[mt][nt][1]);
                redg_add_f32(p1,     acc[mt][nt][2]);
                redg_add_f32(p1 + 1, acc[mt][nt][3]);
            }
        }
    }
}

// ---------------------------------------------------------------------------
// Host side
// ---------------------------------------------------------------------------
extern "C" void kernel_launch(void* const* d_in, const int* in_sizes, int n_in,
                              void* d_out, int out_size) {
    const float* x    = (const float*)d_in[0];
    const float* w    = (const float*)d_in[1];
    const float* bias = (const float*)d_in[2];
    float* out = (float*)d_out;

    __half *xh, *wh;
    cudaGetSymbolAddress((void**)&xh, g_xh);
    cudaGetSymbolAddress((void**)&wh, g_wh);

    // 0. pre-fill tail-tile region of out with bias (before GEMM's REDG adds)
    {
        int total4 = A4_COUNT + B4_COUNT;    // 557056
        init_tail_kernel<<<(total4 + 255) / 256, 256>>>(
            (float4*)out, (const float4*)bias);
    }

    // 1. convert x, W to fp16
    {
        int n16x = (M_TOTAL * K_TOTAL) / 16;   // 1,048,576
        int n16w = (N_TOTAL * K_TOTAL) / 16;   //   262,144
        int total = n16x + n16w;
        convert_both_kernel<<<(total + 255) / 256, 256>>>(
            (const float4*)x, (float4*)xh, n16x,
            (const float4*)w, (float4*)wh, n16w);
    }

    // 2. GEMM: 888 full-K tiles + 272 half-K tail CTAs
    static bool attr_set = false;
    if (!attr_set) {
        cudaFuncSetAttribute(fp16_gemm_kernel,
                             cudaFuncAttributeMaxDynamicSharedMemorySize, SMEM_REQ);
        attr_set = true;
    }
    fp16_gemm_kernel<<<GRID_SIZE, 128, SMEM_REQ>>>(out, bias, xh, wh);
}

// round 14
// speedup vs baseline: 1.2582x; 1.1483x over previous
#include <cuda_runtime.h>
#include <cuda_fp16.h>
#include <cstdint>

// ============================================================================
// out[8192,2048] = x[8192,2048] @ W[2048,2048]^T + bias
// fp16 single-term GEMM on HMMA (mma.sync m16n8k16.f32.f16.f16.f32).
// R14: persistent CTAs + work-stealing, continuous cross-tile cp.async stream.
//   - R9 CTA shape verbatim: 128 thr, tile 128x128, KT=64, 3-stage ring,
//     96KB smem, 2 CTAs/SM, warp tile 64x64, stage-head reorder.
//   - grid 304 persistent CTAs; tiles claimed via atomic counter (reset by
//     the convert kernel, stream-ordered). Chunk pipeline never drains at
//     tile boundaries: ks=30,31 load next tile's chunks 0,1; epilogue STG
//     overlaps next tile's loads.
// ============================================================================

#define M_TOTAL 8192
#define N_TOTAL 2048
#define K_TOTAL 2048

#define MT 128
#define NT 128
#define KT 64
#define KITERS 32               // per tile
#define NSTAGE 3

#define M_TILES (M_TOTAL / MT)  // 64
#define N_TILES (N_TOTAL / NT)  // 16
#define NUM_TILES (M_TILES * N_TILES)   // 1024

#define NPERSIST 304            // 2 CTAs/SM x 152 SMs (GB300)

#define OFF_A 0
#define OFF_B 16384
#define STAGE_BYTES 32768
#define SMEM_REQ (NSTAGE * STAGE_BYTES + 16)   // +16 for s_next slot

__device__ __half g_xh[M_TOTAL * K_TOTAL];
__device__ __half g_wh[N_TOTAL * K_TOTAL];
__device__ int g_tile_ctr;

// ---------------------------------------------------------------------------
__device__ __forceinline__ uint32_t smem_u32(const void* p) {
    uint32_t a;
    asm("{ .reg .u64 t; cvta.to.shared.u64 t, %1; cvt.u32.u64 %0, t; }"
        : "=r"(a) : "l"(p));
    return a;
}

__device__ __forceinline__ void cp_async16(uint32_t dst, const void* src) {
    asm volatile("cp.async.cg.shared.global [%0], [%1], 16;"
                 :: "r"(dst), "l"(src));
}
#define CP_COMMIT() asm volatile("cp.async.commit_group;" ::: "memory")
#define CP_WAIT1()  asm volatile("cp.async.wait_group 1;" ::: "memory")

__device__ __forceinline__ void ldsm_x4(uint32_t* r, uint32_t addr) {
    asm volatile("ldmatrix.sync.aligned.m8n8.x4.shared.b16 {%0,%1,%2,%3}, [%4];"
                 : "=r"(r[0]), "=r"(r[1]), "=r"(r[2]), "=r"(r[3])
                 : "r"(addr));
}

__device__ __forceinline__ void mma16816(float* c, const uint32_t* a, const uint32_t* b) {
    asm volatile(
        "mma.sync.aligned.m16n8k16.row.col.f32.f16.f16.f32 "
        "{%0,%1,%2,%3}, {%4,%5,%6,%7}, {%8,%9}, {%0,%1,%2,%3};"
        : "+f"(c[0]), "+f"(c[1]), "+f"(c[2]), "+f"(c[3])
        : "r"(a[0]), "r"(a[1]), "r"(a[2]), "r"(a[3]),
          "r"(b[0]), "r"(b[1]));
}

// ---------------------------------------------------------------------------
// Kernel 1: convert fp32 -> fp16 for BOTH x and W; resets tile counter.
// ---------------------------------------------------------------------------
__global__ void __launch_bounds__(256) convert_both_kernel(
    const float4* __restrict__ srcx, float4* __restrict__ dstx, int n16x,
    const float4* __restrict__ srcw, float4* __restrict__ dstw, int n16w)
{
    if (blockIdx.x == 0 && threadIdx.x == 0) g_tile_ctr = 0;

    int i = blockIdx.x * blockDim.x + threadIdx.x;
    const float4* src;
    float4* dst;
    if (i < n16x) {
        src = srcx + 4 * (size_t)i;
        dst = dstx + 2 * (size_t)i;
    } else {
        int j = i - n16x;
        if (j >= n16w) return;
        src = srcw + 4 * (size_t)j;
        dst = dstw + 2 * (size_t)j;
    }
    float4 v0 = src[0];
    float4 v1 = src[1];
    float4 v2 = src[2];
    float4 v3 = src[3];

    __half2 h0 = __halves2half2(__float2half_rn(v0.x), __float2half_rn(v0.y));
    __half2 h1 = __halves2half2(__float2half_rn(v0.z), __float2half_rn(v0.w));
    __half2 h2 = __halves2half2(__float2half_rn(v1.x), __float2half_rn(v1.y));
    __half2 h3 = __halves2half2(__float2half_rn(v1.z), __float2half_rn(v1.w));
    __half2 h4 = __halves2half2(__float2half_rn(v2.x), __float2half_rn(v2.y));
    __half2 h5 = __halves2half2(__float2half_rn(v2.z), __float2half_rn(v2.w));
    __half2 h6 = __halves2half2(__float2half_rn(v3.x), __float2half_rn(v3.y));
    __half2 h7 = __halves2half2(__float2half_rn(v3.z), __float2half_rn(v3.w));

    float4 o0, o1;
    o0.x = __uint_as_float(*(uint32_t*)&h0);
    o0.y = __uint_as_float(*(uint32_t*)&h1);
    o0.z = __uint_as_float(*(uint32_t*)&h2);
    o0.w = __uint_as_float(*(uint32_t*)&h3);
    o1.x = __uint_as_float(*(uint32_t*)&h4);
    o1.y = __uint_as_float(*(uint32_t*)&h5);
    o1.z = __uint_as_float(*(uint32_t*)&h6);
    o1.w = __uint_as_float(*(uint32_t*)&h7);
    dst[0] = o0;
    dst[1] = o1;
}

// ---------------------------------------------------------------------------
// Kernel 2: persistent fp16 GEMM, continuous cross-tile pipeline.
// ---------------------------------------------------------------------------
__global__ void __launch_bounds__(128, 2) fp16_gemm_kernel(
    float* __restrict__ out,
    const float* __restrict__ bias,
    const __half* __restrict__ xh,
    const __half* __restrict__ wh)
{
    extern __shared__ __align__(1024) char smem[];
    const uint32_t sb = smem_u32(smem);
    int* s_next = (int*)(smem + NSTAGE * STAGE_BYTES);

    const int tid = threadIdx.x;
    const int lane = tid & 31;
    const int wid = tid >> 5;
    const int warp_m = wid >> 1;   // 0..1
    const int warp_n = wid & 1;    // 0..1

    // ---- loader thread layout (R9) ----
    const int lrow = tid >> 3;
    const int lchk = tid & 7;
    const uint32_t dsw0 = (uint32_t)(lrow * 128 + ((lchk ^ (lrow & 7)) << 4));

    auto baseA = [&](int t) {
        return xh + (size_t)((t >> 4) * MT + lrow) * K_TOTAL + lchk * 8;
    };
    auto baseB = [&](int t) {
        return wh + (size_t)((t & (N_TILES - 1)) * NT + lrow) * K_TOTAL + lchk * 8;
    };

    auto load_stage = [&](int stage, const __half* pA, const __half* pB) {
        uint32_t sbase = sb + stage * STAGE_BYTES + dsw0;
#pragma unroll
        for (int i = 0; i < 8; i++) {
            cp_async16(sbase + OFF_A + i * 2048, pA + (size_t)i * (16 * K_TOTAL));
            cp_async16(sbase + OFF_B + i * 2048, pB + (size_t)i * (16 * K_TOTAL));
        }
    };

    // ---- ldmatrix per-lane base terms ----
    const int a_row_l = warp_m * 64 + (lane & 15);
    const int a_kadd  = lane >> 4;
    const int b_row_l = warp_n * 64 + (lane & 7) + ((lane >> 4) << 3);
    const int b_kadd  = (lane >> 3) & 1;

    uint32_t a[4][4], b[8][2];
    auto ld_frags = [&](int kc, uint32_t sA, uint32_t sB) {
#pragma unroll
        for (int mt = 0; mt < 4; mt++) {
            int row = a_row_l + mt * 16;
            int ch = kc * 2 + a_kadd;
            uint32_t off = (uint32_t)(row * 128 + ((ch ^ (row & 7)) << 4));
            ldsm_x4(a[mt], sA + off);
        }
#pragma unroll
        for (int np = 0; np < 4; np++) {
            int row = b_row_l + np * 16;
            int ch = kc * 2 + b_kadd;
            uint32_t off = (uint32_t)(row * 128 + ((ch ^ (row & 7)) << 4));
            uint32_t t[4];
            ldsm_x4(t, sB + off);
            b[np * 2][0] = t[0]; b[np * 2][1] = t[1];
            b[np * 2 + 1][0] = t[2]; b[np * 2 + 1][1] = t[3];
        }
    };

    // ---- claim first tile ----
    if (tid == 0) s_next[0] = atomicAdd(&g_tile_ctr, 1);
    __syncthreads();
    int tile = s_next[0];
    if (tile >= NUM_TILES) return;

    const __half* cA = baseA(tile);
    const __half* cB = baseB(tile);

    // prologue: chunks 0,1 of first tile -> stages 0,1
    load_stage(0, cA, cB);
    CP_COMMIT();
    load_stage(1, cA + KT, cB + KT);
    CP_COMMIT();

    float acc[4][8][4];
#pragma unroll
    for (int mt = 0; mt < 4; mt++)
#pragma unroll
        for (int nt = 0; nt < 8; nt++)
#pragma unroll
            for (int j = 0; j < 4; j++) acc[mt][nt][j] = 0.0f;

    int ring = 0;

    while (true) {
        // claim next tile (published by the ks=0 __syncthreads below)
        if (tid == 0) s_next[0] = atomicAdd(&g_tile_ctr, 1);

        int next_tile = NUM_TILES;
        const __half* nA = cA;
        const __half* nB = cB;

        for (int ks = 0; ks < KITERS; ks++) {
            CP_WAIT1();
            __syncthreads();
            if (ks == 0) next_tile = s_next[0];

            const uint32_t sbase = sb + ring * STAGE_BYTES;
            const uint32_t sA = sbase + OFF_A;
            const uint32_t sB = sbase + OFF_B;

            // kc0 frag loads first (stage-head reorder)
            ld_frags(0, sA, sB);

            // load chunk ks+2 (possibly next tile's chunk 0/1)
            int lks = ks + 2;
            int lstage = ring + 2;
            if (lstage >= NSTAGE) lstage -= NSTAGE;
            if (lks < KITERS) {
                load_stage(lstage, cA + lks * KT, cB + lks * KT);
            } else if (next_tile < NUM_TILES) {
                if (ks == KITERS - 2) { nA = baseA(next_tile); nB = baseB(next_tile); }
                load_stage(lstage, nA + (lks - KITERS) * KT, nB + (lks - KITERS) * KT);
            }
            CP_COMMIT();

#pragma unroll
            for (int kc = 0; kc < 4; kc++) {
#pragma unroll
                for (int mt = 0; mt < 4; mt++) {
#pragma unroll
                    for (int nt = 0; nt < 8; nt++) {
                        mma16816(acc[mt][nt], a[mt], b[nt]);
                    }
                }
                if (kc < 3) ld_frags(kc + 1, sA, sB);
            }

            ring = (ring == NSTAGE - 1) ? 0 : ring + 1;
        }

        // ---- epilogue for `tile` (STG overlaps next tile's in-flight loads) ----
        {
            const int m0 = (tile >> 4) * MT;
            const int n0 = (tile & (N_TILES - 1)) * NT;
            const int r0 = lane >> 2;
            const int c0 = (lane & 3) * 2;
#pragma unroll
            for (int mt = 0; mt < 4; mt++) {
                int row = m0 + warp_m * 64 + mt * 16 + r0;
#pragma unroll
                for (int nt = 0; nt < 8; nt++) {
                    int col = n0 + warp_n * 64 + nt * 8 + c0;
                    float bx = __ldg(bias + col);
                    float by = __ldg(bias + col + 1);
                    float2 v0 = make_float2(acc[mt][nt][0] + bx, acc[mt][nt][1] + by);
                    float2 v1 = make_float2(acc[mt][nt][2] + bx, acc[mt][nt][3] + by);
                    *(float2*)(out + (size_t)row * N_TOTAL + col) = v0;
                    *(float2*)(out + (size_t)(row + 8) * N_TOTAL + col) = v1;
                    acc[mt][nt][0] = 0.0f; acc[mt][nt][1] = 0.0f;
                    acc[mt][nt][2] = 0.0f; acc[mt][nt][3] = 0.0f;
                }
            }
        }

        if (next_tile >= NUM_TILES) break;
        tile = next_tile;
        cA = nA;
        cB = nB;
    }
}

// ---------------------------------------------------------------------------
// Host side
// ---------------------------------------------------------------------------
extern "C" void kernel_launch(void* const* d_in, const int* in_sizes, int n_in,
                              void* d_out, int out_size) {
    const float* x    = (const float*)d_in[0];
    const float* w    = (const float*)d_in[1];
    const float* bias = (const float*)d_in[2];
    float* out = (float*)d_out;

    __half *xh, *wh;
    cudaGetSymbolAddress((void**)&xh, g_xh);
    cudaGetSymbolAddress((void**)&wh, g_wh);

    // 1. convert x, W to fp16 (also resets the persistent-tile counter)
    {
        int n16x = (M_TOTAL * K_TOTAL) / 16;   // 1,048,576
        int n16w = (N_TOTAL * K_TOTAL) / 16;   //   262,144
        int total = n16x + n16w;
        convert_both_kernel<<<(total + 255) / 256, 256>>>(
            (const float4*)x, (float4*)xh, n16x,
            (const float4*)w, (float4*)wh, n16w);
    }

    // 2. persistent GEMM
    static bool attr_set = false;
    if (!attr_set) {
        cudaFuncSetAttribute(fp16_gemm_kernel,
                             cudaFuncAttributeMaxDynamicSharedMemorySize, SMEM_REQ);
        attr_set = true;
    }
    fp16_gemm_kernel<<<NPERSIST, 128, SMEM_REQ>>>(out, bias, xh, wh);
}